// round 10
// baseline (speedup 1.0000x reference)
#include <cuda_runtime.h>
#include <cuda_bf16.h>
#include <math.h>
#include <stdint.h>

#define B_   8
#define S_   4096
#define D_   256
#define SEG_ 128
#define E_   32
#define MASKVAL (-3.402823466e38f)

#define SEQ_ST 264   // halves
#define WB_ST  24    // halves
#define ATT_ST 136   // halves

// smem byte offsets
#define OFF_SEQ_H 0          // 128*264*2 = 67584
#define OFF_SEQ_L 67584
#define OFF_X     135168     // 71680 scratch: wbuf -> trslo -> exchange/attn
#define OFF_BIAS  206848     // 1024
#define OFF_POOL  207872     // 8 pairs * 256 * 4 = 8192
#define SMEM_TOT  216064

// w packed per 16-wide k-chunk: [kc]{hi 768 uint4 | lo 768 uint4}
__device__ uint4 g_w[16 * 1536];
__device__ int   g_fix[E_];

// ---------------------------------------------------------------------------
__global__ void prep_fix_kernel(const float* __restrict__ w,
                                const float* __restrict__ mask) {
    int e = blockIdx.x, t = threadIdx.x;
    #pragma unroll
    for (int i = 0; i < 8; i++) {
        int idx = (e * 256 + t) + i * 8192;
        int m = idx >> 8, d = idx & 255;
        float v = w[idx];
        __nv_bfloat16 h = __float2bfloat16(v);
        __nv_bfloat16 l = __float2bfloat16(v - __bfloat162float(h));
        int kc = d >> 4, kk = d & 15;
        int off = kc * 12288 + m * 24 + kk;       // halves
        ((__nv_bfloat16*)g_w)[off] = h;
        ((__nv_bfloat16*)g_w)[off + 6144] = l;
    }
    if (t == 0) g_fix[e] = 0;
    __syncthreads();

    int warp = t >> 5, lane = t & 31;
    int found = 0;
    for (int r = warp; r < B_ * SEG_; r += 8) {
        int b = r >> 7, l = r & 127;
        const float* row = mask + ((size_t)b * S_ + (size_t)e * SEG_ + l) * S_
                                + (size_t)e * SEG_;
        int allm = 1;
        #pragma unroll
        for (int k = 0; k < 4; k++)
            if (row[lane + 32 * k] != MASKVAL) allm = 0;
        if (__all_sync(0xffffffffu, allm)) { found = 1; break; }
    }
    if (found && lane == 0) atomicOr(&g_fix[e], 1);
}

// ---------------------------------------------------------------------------
__device__ __forceinline__ void ldsm4(unsigned a, unsigned& r0, unsigned& r1,
                                      unsigned& r2, unsigned& r3) {
    asm volatile("ldmatrix.sync.aligned.m8n8.x4.shared.b16 {%0,%1,%2,%3},[%4];"
                 : "=r"(r0), "=r"(r1), "=r"(r2), "=r"(r3) : "r"(a));
}
__device__ __forceinline__ void ldsm4t(unsigned a, unsigned& r0, unsigned& r1,
                                       unsigned& r2, unsigned& r3) {
    asm volatile("ldmatrix.sync.aligned.m8n8.x4.trans.shared.b16 {%0,%1,%2,%3},[%4];"
                 : "=r"(r0), "=r"(r1), "=r"(r2), "=r"(r3) : "r"(a));
}
__device__ __forceinline__ void mma16816(float* c, unsigned a0, unsigned a1,
                                         unsigned a2, unsigned a3,
                                         unsigned b0, unsigned b1) {
    asm volatile(
        "mma.sync.aligned.m16n8k16.row.col.f32.bf16.bf16.f32 "
        "{%0,%1,%2,%3},{%4,%5,%6,%7},{%8,%9},{%0,%1,%2,%3};"
        : "+f"(c[0]), "+f"(c[1]), "+f"(c[2]), "+f"(c[3])
        : "r"(a0), "r"(a1), "r"(a2), "r"(a3), "r"(b0), "r"(b1));
}
__device__ __forceinline__ unsigned packhi(float a, float b) {
    __nv_bfloat162 p;
    p.x = __float2bfloat16(a); p.y = __float2bfloat16(b);
    return *(unsigned*)&p;
}
__device__ __forceinline__ unsigned packlo(float a, float b, unsigned hi) {
    __nv_bfloat162 h = *(__nv_bfloat162*)&hi;
    __nv_bfloat162 p;
    p.x = __float2bfloat16(a - __bfloat162float(h.x));
    p.y = __float2bfloat16(b - __bfloat162float(h.y));
    return *(unsigned*)&p;
}

// ---------------------------------------------------------------------------
__global__ void __launch_bounds__(512, 1)
main_kernel(const float* __restrict__ hidden,
            const float* __restrict__ maskp,
            const float* __restrict__ bvec,
            float* __restrict__ out)
{
    extern __shared__ char smc[];
    const unsigned sb = (unsigned)__cvta_generic_to_shared(smc);

    float* bias = (float*)(smc + OFF_BIAS);
    float* pool = (float*)(smc + OFF_POOL);

    const int t = threadIdx.x;
    const int lane = t & 31, wi = t >> 5;
    const int pr = wi >> 1, wc = wi & 1;           // pair / half
    const int rg = lane >> 2, tg = lane & 3;
    const int e = blockIdx.x, bb = blockIdx.y;

    // ---- load seq tile, split bf16 hi/lo ----
    const float* seq_g = hidden + ((size_t)bb * S_ + (size_t)e * SEG_) * D_;
    for (int i = t; i < SEG_ * D_ / 4; i += 512) {
        int l = i >> 6, d = (i & 63) << 2;
        float4 v = *(const float4*)(seq_g + l * D_ + d);
        __nv_bfloat162 h0, h1, l0, l1;
        h0.x = __float2bfloat16(v.x); h0.y = __float2bfloat16(v.y);
        h1.x = __float2bfloat16(v.z); h1.y = __float2bfloat16(v.w);
        l0.x = __float2bfloat16(v.x - __bfloat162float(h0.x));
        l0.y = __float2bfloat16(v.y - __bfloat162float(h0.y));
        l1.x = __float2bfloat16(v.z - __bfloat162float(h1.x));
        l1.y = __float2bfloat16(v.w - __bfloat162float(h1.y));
        __nv_bfloat16* sh = (__nv_bfloat16*)(smc + OFF_SEQ_H) + l * SEQ_ST + d;
        __nv_bfloat16* sl = (__nv_bfloat16*)(smc + OFF_SEQ_L) + l * SEQ_ST + d;
        *(__nv_bfloat162*)sh = h0; *(__nv_bfloat162*)(sh + 2) = h1;
        *(__nv_bfloat162*)sl = l0; *(__nv_bfloat162*)(sl + 2) = l1;
    }
    if (t < 256) bias[t] = bvec[t];
    const int fixe = g_fix[e];

    // w chunk fetch/store (chunk = 1536 uint4; per thread 3)
    uint4 f0, f1, f2;
    auto fetch = [&](int cc) {
        const uint4* g = g_w + cc * 1536;
        f0 = g[t]; f1 = g[t + 512]; f2 = g[t + 1024];
    };
    auto wstore = [&](int bufi) {
        char* base = smc + OFF_X + bufi * 24576;
        *(uint4*)(base + t * 16) = f0;
        *(uint4*)(base + 8192 + t * 16) = f1;
        *(uint4*)(base + 16384 + t * 16) = f2;
    };

    auto adrA = [&](unsigned off, int st, int r0, int k0) -> unsigned {
        int r = r0 + (lane & 7) + ((lane >> 3) & 1) * 8;
        int c = k0 + ((lane >> 4) & 1) * 8;
        return sb + off + (unsigned)((r * st + c) * 2);
    };
    auto adrB = [&](unsigned off, int st, int n0, int k0) -> unsigned {
        int r = n0 + (lane & 7) + ((lane >> 4) & 1) * 8;
        int c = k0 + ((lane >> 3) & 1) * 8;
        return sb + off + (unsigned)((r * st + c) * 2);
    };
    auto adrBt = [&](unsigned off, int st, int k0, int d0) -> unsigned {
        int r = k0 + (lane & 7) + ((lane >> 3) & 1) * 8;
        int c = d0 + ((lane >> 4) & 1) * 8;
        return sb + off + (unsigned)((r * st + c) * 2);
    };

    fetch(0);
    __syncthreads();     // seq smem ready
    wstore(0);
    __syncthreads();

    // ===== Phase A: accA = seq(pair's 16 rows) @ w^T (warp's 128-m half) ===
    float accA[16][4];
    #pragma unroll
    for (int j = 0; j < 16; j++)
        #pragma unroll
        for (int q = 0; q < 4; q++) accA[j][q] = 0.0f;

    for (int kc = 0; kc < 16; kc++) {
        if (kc < 15) fetch(kc + 1);
        unsigned ah0, ah1, ah2, ah3, am0, am1, am2, am3;
        ldsm4(adrA(OFF_SEQ_H, SEQ_ST, pr * 16, kc * 16), ah0, ah1, ah2, ah3);
        ldsm4(adrA(OFF_SEQ_L, SEQ_ST, pr * 16, kc * 16), am0, am1, am2, am3);
        unsigned bufH = OFF_X + (unsigned)(kc & 1) * 24576;
        unsigned bufL = bufH + 12288;
        #pragma unroll
        for (int p = 0; p < 8; p++) {
            unsigned bh0, bh1, bh2, bh3, bl0, bl1, bl2, bl3;
            ldsm4(adrB(bufH, WB_ST, wc * 128 + p * 16, 0), bh0, bh1, bh2, bh3);
            ldsm4(adrB(bufL, WB_ST, wc * 128 + p * 16, 0), bl0, bl1, bl2, bl3);
            mma16816(accA[2*p],   ah0, ah1, ah2, ah3, bh0, bh1);
            mma16816(accA[2*p],   ah0, ah1, ah2, ah3, bl0, bl1);
            mma16816(accA[2*p],   am0, am1, am2, am3, bh0, bh1);
            mma16816(accA[2*p+1], ah0, ah1, ah2, ah3, bh2, bh3);
            mma16816(accA[2*p+1], ah0, ah1, ah2, ah3, bl2, bl3);
            mma16816(accA[2*p+1], am0, am1, am2, am3, bh2, bh3);
        }
        if (kc < 15) wstore((kc + 1) & 1);
        __syncthreads();   // also phase-A end barrier before trslo writes
    }

    // ===== epilogue: bias + tanh; hi frags -> regs, lo -> warp smem (X) ====
    unsigned pAh[32];
    const unsigned trsloW = OFF_X + (unsigned)wi * 4480;
    #pragma unroll
    for (int j = 0; j < 16; j++) {
        int m0 = wc * 128 + j * 8 + tg * 2;
        float b0 = bias[m0], b1 = bias[m0 + 1];
        float v0 = tanhf(accA[j][0] + b0), v1 = tanhf(accA[j][1] + b1);
        float v2 = tanhf(accA[j][2] + b0), v3 = tanhf(accA[j][3] + b1);
        int base = (j >> 1) * 4 + (j & 1) * 2;
        pAh[base]     = packhi(v0, v1);
        pAh[base + 1] = packhi(v2, v3);
        unsigned lo01 = packlo(v0, v1, pAh[base]);
        unsigned lo23 = packlo(v2, v3, pAh[base + 1]);
        *(unsigned*)(smc + trsloW + (unsigned)((rg * ATT_ST + j * 8 + tg * 2) * 2)) = lo01;
        *(unsigned*)(smc + trsloW + (unsigned)(((rg + 8) * ATT_ST + j * 8 + tg * 2) * 2)) = lo23;
    }
    __syncwarp();

    // ===== Phase B: partial scores over warp's m-half =====================
    float accB[16][4];
    #pragma unroll
    for (int j = 0; j < 16; j++)
        #pragma unroll
        for (int q = 0; q < 4; q++) accB[j][q] = 0.0f;

    #pragma unroll
    for (int q = 0; q < 8; q++) {          // pass 1: hi terms
        int kq = (wc * 8 + q) * 16;
        #pragma unroll
        for (int p = 0; p < 8; p++) {
            unsigned bh0, bh1, bh2, bh3, bl0, bl1, bl2, bl3;
            ldsm4(adrB(OFF_SEQ_H, SEQ_ST, p * 16, kq), bh0, bh1, bh2, bh3);
            ldsm4(adrB(OFF_SEQ_L, SEQ_ST, p * 16, kq), bl0, bl1, bl2, bl3);
            mma16816(accB[2*p],   pAh[q*4], pAh[q*4+1], pAh[q*4+2], pAh[q*4+3], bh0, bh1);
            mma16816(accB[2*p],   pAh[q*4], pAh[q*4+1], pAh[q*4+2], pAh[q*4+3], bl0, bl1);
            mma16816(accB[2*p+1], pAh[q*4], pAh[q*4+1], pAh[q*4+2], pAh[q*4+3], bh2, bh3);
            mma16816(accB[2*p+1], pAh[q*4], pAh[q*4+1], pAh[q*4+2], pAh[q*4+3], bl2, bl3);
        }
    }
    #pragma unroll
    for (int q = 0; q < 8; q++) {          // pass 2: lo @ seq_hi
        unsigned Al0, Al1, Al2, Al3;
        ldsm4(adrA(trsloW, ATT_ST, 0, q * 16), Al0, Al1, Al2, Al3);
        int kq = (wc * 8 + q) * 16;
        #pragma unroll
        for (int p = 0; p < 8; p++) {
            unsigned bh0, bh1, bh2, bh3;
            ldsm4(adrB(OFF_SEQ_H, SEQ_ST, p * 16, kq), bh0, bh1, bh2, bh3);
            mma16816(accB[2*p],   Al0, Al1, Al2, Al3, bh0, bh1);
            mma16816(accB[2*p+1], Al0, Al1, Al2, Al3, bh2, bh3);
        }
    }
    __syncthreads();      // trslo dead; X reusable for exchange/attn

    // ===== pair exchange + softmax (wc==0) ================================
    const unsigned xp = OFF_X + (unsigned)pr * 8960;
    if (wc == 1) {
        #pragma unroll
        for (int j = 0; j < 16; j++) {
            float4 v = make_float4(accB[j][0], accB[j][1], accB[j][2], accB[j][3]);
            *(float4*)(smc + xp + (unsigned)((j * 32 + lane) * 16)) = v;
        }
    }
    __syncthreads();
    if (wc == 0) {
        #pragma unroll
        for (int j = 0; j < 16; j++) {
            float4 v = *(const float4*)(smc + xp + (unsigned)((j * 32 + lane) * 16));
            accB[j][0] += v.x; accB[j][1] += v.y;
            accB[j][2] += v.z; accB[j][3] += v.w;
        }
        __syncwarp();
        // mask add + softmax, rows l0 and l0+8
        int l0 = pr * 16 + rg;
        const float* mr0 = maskp + ((size_t)(bb * S_ + e * SEG_ + l0)) * S_
                                 + (size_t)e * SEG_;
        const float* mr1 = mr0 + (size_t)8 * S_;
        #pragma unroll
        for (int j = 0; j < 16; j++) {
            float2 m0 = *(const float2*)(mr0 + 8 * j + tg * 2);
            float2 m1 = *(const float2*)(mr1 + 8 * j + tg * 2);
            if (fixe && l0 == 0) { m0.x = 0.0f; m0.y = 0.0f; }
            accB[j][0] += m0.x; accB[j][1] += m0.y;
            accB[j][2] += m1.x; accB[j][3] += m1.y;
        }
        float mx0 = -3.4e38f, mx1 = -3.4e38f;
        #pragma unroll
        for (int j = 0; j < 16; j++) {
            mx0 = fmaxf(mx0, fmaxf(accB[j][0], accB[j][1]));
            mx1 = fmaxf(mx1, fmaxf(accB[j][2], accB[j][3]));
        }
        mx0 = fmaxf(mx0, __shfl_xor_sync(0xffffffffu, mx0, 1));
        mx0 = fmaxf(mx0, __shfl_xor_sync(0xffffffffu, mx0, 2));
        mx1 = fmaxf(mx1, __shfl_xor_sync(0xffffffffu, mx1, 1));
        mx1 = fmaxf(mx1, __shfl_xor_sync(0xffffffffu, mx1, 2));
        float s0 = 0.0f, s1 = 0.0f;
        #pragma unroll
        for (int j = 0; j < 16; j++) {
            accB[j][0] = expf(accB[j][0] - mx0);
            accB[j][1] = expf(accB[j][1] - mx0);
            accB[j][2] = expf(accB[j][2] - mx1);
            accB[j][3] = expf(accB[j][3] - mx1);
            s0 += accB[j][0] + accB[j][1];
            s1 += accB[j][2] + accB[j][3];
        }
        s0 += __shfl_xor_sync(0xffffffffu, s0, 1);
        s0 += __shfl_xor_sync(0xffffffffu, s0, 2);
        s1 += __shfl_xor_sync(0xffffffffu, s1, 1);
        s1 += __shfl_xor_sync(0xffffffffu, s1, 2);
        float i0 = 1.0f / s0, i1 = 1.0f / s1;
        // write attn hi/lo (overwrites exchange region, reads complete)
        #pragma unroll
        for (int j = 0; j < 16; j++) {
            float a0 = accB[j][0] * i0, a1 = accB[j][1] * i0;
            float a2 = accB[j][2] * i1, a3 = accB[j][3] * i1;
            unsigned h01 = packhi(a0, a1), h23 = packhi(a2, a3);
            unsigned l01 = packlo(a0, a1, h01), l23 = packlo(a2, a3, h23);
            unsigned o0 = (unsigned)((rg * ATT_ST + j * 8 + tg * 2) * 2);
            unsigned o1 = (unsigned)(((rg + 8) * ATT_ST + j * 8 + tg * 2) * 2);
            *(unsigned*)(smc + xp + o0) = h01;
            *(unsigned*)(smc + xp + o1) = h23;
            *(unsigned*)(smc + xp + 4352 + o0) = l01;
            *(unsigned*)(smc + xp + 4352 + o1) = l23;
        }
    }
    __syncthreads();

    // ===== Phase C: ctx(16 rows x warp's 128-d half) = attn @ seq =========
    float accC[16][4];
    #pragma unroll
    for (int j = 0; j < 16; j++)
        #pragma unroll
        for (int q = 0; q < 4; q++) accC[j][q] = 0.0f;

    #pragma unroll
    for (int kc = 0; kc < 8; kc++) {
        unsigned aH0, aH1, aH2, aH3, aL0, aL1, aL2, aL3;
        ldsm4(adrA(xp, ATT_ST, 0, kc * 16), aH0, aH1, aH2, aH3);
        ldsm4(adrA(xp + 4352, ATT_ST, 0, kc * 16), aL0, aL1, aL2, aL3);
        #pragma unroll
        for (int p = 0; p < 8; p++) {
            int d0 = wc * 128 + p * 16;
            unsigned bh0, bh1, bh2, bh3, bl0, bl1, bl2, bl3;
            ldsm4t(adrBt(OFF_SEQ_H, SEQ_ST, kc * 16, d0), bh0, bh1, bh2, bh3);
            ldsm4t(adrBt(OFF_SEQ_L, SEQ_ST, kc * 16, d0), bl0, bl1, bl2, bl3);
            mma16816(accC[2*p],   aH0, aH1, aH2, aH3, bh0, bh1);
            mma16816(accC[2*p],   aH0, aH1, aH2, aH3, bl0, bl1);
            mma16816(accC[2*p],   aL0, aL1, aL2, aL3, bh0, bh1);
            mma16816(accC[2*p+1], aH0, aH1, aH2, aH3, bh2, bh3);
            mma16816(accC[2*p+1], aH0, aH1, aH2, aH3, bl2, bl3);
            mma16816(accC[2*p+1], aL0, aL1, aL2, aL3, bh2, bh3);
        }
    }
    // pool over the pair's 16 rows
    #pragma unroll
    for (int j = 0; j < 16; j++) {
        float m0 = fmaxf(accC[j][0], accC[j][2]);
        float m1 = fmaxf(accC[j][1], accC[j][3]);
        m0 = fmaxf(m0, __shfl_xor_sync(0xffffffffu, m0, 4));
        m0 = fmaxf(m0, __shfl_xor_sync(0xffffffffu, m0, 8));
        m0 = fmaxf(m0, __shfl_xor_sync(0xffffffffu, m0, 16));
        m1 = fmaxf(m1, __shfl_xor_sync(0xffffffffu, m1, 4));
        m1 = fmaxf(m1, __shfl_xor_sync(0xffffffffu, m1, 8));
        m1 = fmaxf(m1, __shfl_xor_sync(0xffffffffu, m1, 16));
        if (rg == 0) {
            int d = wc * 128 + 8 * j + tg * 2;
            pool[pr * 256 + d]     = m0;
            pool[pr * 256 + d + 1] = m1;
        }
    }
    __syncthreads();

    // ---- final pool reduce over 8 pairs ----
    if (t < 256) {
        float mx = -3.4e38f;
        #pragma unroll
        for (int p = 0; p < 8; p++) mx = fmaxf(mx, pool[p * 256 + t]);
        out[((size_t)bb * E_ + e) * D_ + t] = mx;
    }

    // new_mask[b][e][s] = (s/128 == e)
    float* nm = out + (size_t)B_ * E_ * D_ + ((size_t)bb * E_ + e) * S_;
    for (int s = t; s < S_; s += 512)
        nm[s] = ((s >> 7) == e) ? 1.0f : 0.0f;
}

// ---------------------------------------------------------------------------
extern "C" void kernel_launch(void* const* d_in, const int* in_sizes, int n_in,
                              void* d_out, int out_size) {
    const float* hidden = (const float*)d_in[0];
    const float* mask   = (const float*)d_in[1];
    const float* w      = (const float*)d_in[2];
    const float* bvec   = (const float*)d_in[3];
    float* out = (float*)d_out;
    (void)in_sizes; (void)n_in; (void)out_size;

    prep_fix_kernel<<<E_, 256>>>(w, mask);

    cudaFuncSetAttribute(main_kernel,
                         cudaFuncAttributeMaxDynamicSharedMemorySize, SMEM_TOT);
    main_kernel<<<dim3(E_, B_), 512, SMEM_TOT>>>(hidden, mask, bvec, out);
}

// round 11
// speedup vs baseline: 1.4561x; 1.4561x over previous
#include <cuda_runtime.h>
#include <cuda_bf16.h>
#include <math.h>
#include <stdint.h>

#define B_   8
#define S_   4096
#define D_   256
#define SEG_ 128
#define E_   32
#define MASKVAL (-3.402823466e38f)

#define SEQ_ST 264   // halves
#define WB_ST  40    // halves (pad: conflict-free ldsm at 80B row stride)

// smem byte offsets
#define OFF_SEQ_H 0          // 128*264*2 = 67584
#define OFF_SEQ_L 67584      // ends 135168
#define OFF_WBUF  135168     // 2 bufs x 20480 = 40960, ends 176128
#define OFF_BIAS  176128     // 1024
#define OFF_POOL  177152     // 8*256*4 = 8192
#define SMEM_TOT  185344

// w packed per chunk j = h*8 + c (h = m-half, c = 32-wide k chunk):
// [j]{ hi: m 0..127 x 40 halves | lo: same } = 10240 halves per chunk
__device__ __nv_bfloat16 g_w[16 * 10240];
__device__ int g_fix[E_];

// ---------------------------------------------------------------------------
__global__ void prep_fix_kernel(const float* __restrict__ w,
                                const float* __restrict__ mask) {
    int e = blockIdx.x, t = threadIdx.x;
    #pragma unroll
    for (int i = 0; i < 8; i++) {
        int idx = (e * 256 + t) + i * 8192;       // 65536 total
        int m = idx >> 8, d = idx & 255;
        float v = w[idx];
        __nv_bfloat16 h = __float2bfloat16(v);
        __nv_bfloat16 l = __float2bfloat16(v - __bfloat162float(h));
        int hh = m >> 7, mloc = m & 127, c = d >> 5, kk = d & 31;
        int j = hh * 8 + c;
        int off = j * 10240 + mloc * 40 + kk;
        g_w[off] = h;
        g_w[off + 5120] = l;
    }
    if (t == 0) g_fix[e] = 0;
    __syncthreads();

    int warp = t >> 5, lane = t & 31;
    int found = 0;
    for (int r = warp; r < B_ * SEG_; r += 8) {
        int b = r >> 7, l = r & 127;
        const float* row = mask + ((size_t)b * S_ + (size_t)e * SEG_ + l) * S_
                                + (size_t)e * SEG_;
        int allm = 1;
        #pragma unroll
        for (int k = 0; k < 4; k++)
            if (row[lane + 32 * k] != MASKVAL) allm = 0;
        if (__all_sync(0xffffffffu, allm)) { found = 1; break; }
    }
    if (found && lane == 0) atomicOr(&g_fix[e], 1);
}

// ---------------------------------------------------------------------------
__device__ __forceinline__ void ldsm4(unsigned a, unsigned& r0, unsigned& r1,
                                      unsigned& r2, unsigned& r3) {
    asm volatile("ldmatrix.sync.aligned.m8n8.x4.shared.b16 {%0,%1,%2,%3},[%4];"
                 : "=r"(r0), "=r"(r1), "=r"(r2), "=r"(r3) : "r"(a));
}
__device__ __forceinline__ void ldsm4t(unsigned a, unsigned& r0, unsigned& r1,
                                       unsigned& r2, unsigned& r3) {
    asm volatile("ldmatrix.sync.aligned.m8n8.x4.trans.shared.b16 {%0,%1,%2,%3},[%4];"
                 : "=r"(r0), "=r"(r1), "=r"(r2), "=r"(r3) : "r"(a));
}
__device__ __forceinline__ void mma16816(float* c, unsigned a0, unsigned a1,
                                         unsigned a2, unsigned a3,
                                         unsigned b0, unsigned b1) {
    asm volatile(
        "mma.sync.aligned.m16n8k16.row.col.f32.bf16.bf16.f32 "
        "{%0,%1,%2,%3},{%4,%5,%6,%7},{%8,%9},{%0,%1,%2,%3};"
        : "+f"(c[0]), "+f"(c[1]), "+f"(c[2]), "+f"(c[3])
        : "r"(a0), "r"(a1), "r"(a2), "r"(a3), "r"(b0), "r"(b1));
}
__device__ __forceinline__ unsigned packhi(float a, float b) {
    __nv_bfloat162 p;
    p.x = __float2bfloat16(a); p.y = __float2bfloat16(b);
    return *(unsigned*)&p;
}
__device__ __forceinline__ unsigned packlo(float a, float b, unsigned hi) {
    __nv_bfloat162 h = *(__nv_bfloat162*)&hi;
    __nv_bfloat162 p;
    p.x = __float2bfloat16(a - __bfloat162float(h.x));
    p.y = __float2bfloat16(b - __bfloat162float(h.y));
    return *(unsigned*)&p;
}
__device__ __forceinline__ void cpasync16(unsigned dst, const void* src) {
    asm volatile("cp.async.cg.shared.global [%0],[%1],16;"
                 :: "r"(dst), "l"(src));
}
#define CP_COMMIT() asm volatile("cp.async.commit_group;" ::: "memory")
#define CP_WAIT0()  asm volatile("cp.async.wait_group 0;" ::: "memory")

// ---------------------------------------------------------------------------
__global__ void __launch_bounds__(256, 1)
main_kernel(const float* __restrict__ hidden,
            const float* __restrict__ maskp,
            const float* __restrict__ bvec,
            float* __restrict__ out)
{
    extern __shared__ char smc[];
    const unsigned sb = (unsigned)__cvta_generic_to_shared(smc);

    float* bias = (float*)(smc + OFF_BIAS);
    float* pool = (float*)(smc + OFF_POOL);

    const int t = threadIdx.x;
    const int lane = t & 31, wi = t >> 5;
    const int rg = lane >> 2, tg = lane & 3;
    const int e = blockIdx.x, bb = blockIdx.y;

    // ---- kick off w chunk 0 (cp.async, overlaps seq load) ----
    auto load_chunk = [&](int j, int bufi) {
        unsigned dst = sb + OFF_WBUF + (unsigned)bufi * 20480 + (unsigned)t * 16;
        const char* src = (const char*)g_w + (size_t)j * 20480 + (size_t)t * 16;
        #pragma unroll
        for (int i = 0; i < 5; i++)
            cpasync16(dst + i * 4096, src + i * 4096);
        CP_COMMIT();
    };
    load_chunk(0, 0);

    // ---- load seq tile, split bf16 hi/lo ----
    const float* seq_g = hidden + ((size_t)bb * S_ + (size_t)e * SEG_) * D_;
    for (int i = t; i < SEG_ * D_ / 4; i += 256) {
        int l = i >> 6, d = (i & 63) << 2;
        float4 v = *(const float4*)(seq_g + l * D_ + d);
        __nv_bfloat162 h0, h1, l0, l1;
        h0.x = __float2bfloat16(v.x); h0.y = __float2bfloat16(v.y);
        h1.x = __float2bfloat16(v.z); h1.y = __float2bfloat16(v.w);
        l0.x = __float2bfloat16(v.x - __bfloat162float(h0.x));
        l0.y = __float2bfloat16(v.y - __bfloat162float(h0.y));
        l1.x = __float2bfloat16(v.z - __bfloat162float(h1.x));
        l1.y = __float2bfloat16(v.w - __bfloat162float(h1.y));
        __nv_bfloat16* sh = (__nv_bfloat16*)(smc + OFF_SEQ_H) + l * SEQ_ST + d;
        __nv_bfloat16* sl = (__nv_bfloat16*)(smc + OFF_SEQ_L) + l * SEQ_ST + d;
        *(__nv_bfloat162*)sh = h0; *(__nv_bfloat162*)(sh + 2) = h1;
        *(__nv_bfloat162*)sl = l0; *(__nv_bfloat162*)(sl + 2) = l1;
    }
    bias[t] = bvec[t];
    const int fixe = g_fix[e];

    auto adrA = [&](unsigned off, int st, int r0, int k0) -> unsigned {
        int r = r0 + (lane & 7) + ((lane >> 3) & 1) * 8;
        int c = k0 + ((lane >> 4) & 1) * 8;
        return sb + off + (unsigned)((r * st + c) * 2);
    };
    auto adrB = [&](unsigned off, int st, int n0, int k0) -> unsigned {
        int r = n0 + (lane & 7) + ((lane >> 4) & 1) * 8;
        int c = k0 + ((lane >> 3) & 1) * 8;
        return sb + off + (unsigned)((r * st + c) * 2);
    };
    auto adrBt = [&](unsigned off, int st, int k0, int d0) -> unsigned {
        int r = k0 + (lane & 7) + ((lane >> 3) & 1) * 8;
        int c = d0 + ((lane >> 4) & 1) * 8;
        return sb + off + (unsigned)((r * st + c) * 2);
    };

    // =========== Phase A: trsf = tanh(seq @ w^T + b), streamed ============
    unsigned pAh[64], pAl[64];              // trsf A-frags, full 256 m
    float accA[16][4];
    #pragma unroll
    for (int j = 0; j < 16; j++)
        #pragma unroll
        for (int q = 0; q < 4; q++) accA[j][q] = 0.0f;

    for (int j = 0; j < 16; j++) {          // chunk: h=j>>3, k32 = j&7
        CP_WAIT0();
        __syncthreads();
        if (j < 15) load_chunk(j + 1, (j + 1) & 1);

        unsigned bufB = OFF_WBUF + (unsigned)(j & 1) * 20480;
        #pragma unroll
        for (int kl = 0; kl < 2; kl++) {
            int kq = (j & 7) * 2 + kl;      // seq k-step 0..15
            unsigned ah0, ah1, ah2, ah3, am0, am1, am2, am3;
            ldsm4(adrA(OFF_SEQ_H, SEQ_ST, wi * 16, kq * 16), ah0, ah1, ah2, ah3);
            ldsm4(adrA(OFF_SEQ_L, SEQ_ST, wi * 16, kq * 16), am0, am1, am2, am3);
            #pragma unroll
            for (int p = 0; p < 8; p++) {
                unsigned bh0, bh1, bh2, bh3, bl0, bl1, bl2, bl3;
                ldsm4(adrB(bufB, WB_ST, p * 16, kl * 16), bh0, bh1, bh2, bh3);
                ldsm4(adrB(bufB + 10240, WB_ST, p * 16, kl * 16), bl0, bl1, bl2, bl3);
                mma16816(accA[2*p],   ah0, ah1, ah2, ah3, bh0, bh1);
                mma16816(accA[2*p],   ah0, ah1, ah2, ah3, bl0, bl1);
                mma16816(accA[2*p],   am0, am1, am2, am3, bh0, bh1);
                mma16816(accA[2*p+1], ah0, ah1, ah2, ah3, bh2, bh3);
                mma16816(accA[2*p+1], ah0, ah1, ah2, ah3, bl2, bl3);
                mma16816(accA[2*p+1], am0, am1, am2, am3, bh2, bh3);
            }
        }

        if ((j & 7) == 7) {
            // epilogue for m-half h: bias + tanh, pack hi/lo frags to regs
            int h = j >> 3;
            #pragma unroll
            for (int jj = 0; jj < 16; jj++) {
                int m0 = h * 128 + jj * 8 + tg * 2;
                float b0 = bias[m0], b1 = bias[m0 + 1];
                float v0 = tanhf(accA[jj][0] + b0), v1 = tanhf(accA[jj][1] + b1);
                float v2 = tanhf(accA[jj][2] + b0), v3 = tanhf(accA[jj][3] + b1);
                int base = h * 32 + (jj >> 1) * 4 + (jj & 1) * 2;
                pAh[base]     = packhi(v0, v1);
                pAl[base]     = packlo(v0, v1, pAh[base]);
                pAh[base + 1] = packhi(v2, v3);
                pAl[base + 1] = packlo(v2, v3, pAh[base + 1]);
                accA[jj][0] = 0.0f; accA[jj][1] = 0.0f;
                accA[jj][2] = 0.0f; accA[jj][3] = 0.0f;
            }
        }
    }

    // =========== Phase B: scores(16 rows x 128 k) = trsf @ seq^T ==========
    float accB[16][4];
    #pragma unroll
    for (int j = 0; j < 16; j++)
        #pragma unroll
        for (int q = 0; q < 4; q++) accB[j][q] = 0.0f;

    #pragma unroll
    for (int kc = 0; kc < 16; kc++) {
        #pragma unroll
        for (int p = 0; p < 8; p++) {
            unsigned bh0, bh1, bh2, bh3, bl0, bl1, bl2, bl3;
            ldsm4(adrB(OFF_SEQ_H, SEQ_ST, p * 16, kc * 16), bh0, bh1, bh2, bh3);
            ldsm4(adrB(OFF_SEQ_L, SEQ_ST, p * 16, kc * 16), bl0, bl1, bl2, bl3);
            mma16816(accB[2*p],   pAh[kc*4], pAh[kc*4+1], pAh[kc*4+2], pAh[kc*4+3], bh0, bh1);
            mma16816(accB[2*p],   pAh[kc*4], pAh[kc*4+1], pAh[kc*4+2], pAh[kc*4+3], bl0, bl1);
            mma16816(accB[2*p],   pAl[kc*4], pAl[kc*4+1], pAl[kc*4+2], pAl[kc*4+3], bh0, bh1);
            mma16816(accB[2*p+1], pAh[kc*4], pAh[kc*4+1], pAh[kc*4+2], pAh[kc*4+3], bh2, bh3);
            mma16816(accB[2*p+1], pAh[kc*4], pAh[kc*4+1], pAh[kc*4+2], pAh[kc*4+3], bl2, bl3);
            mma16816(accB[2*p+1], pAl[kc*4], pAl[kc*4+1], pAl[kc*4+2], pAl[kc*4+3], bh2, bh3);
        }
    }

    // ===== mask add + in-register softmax (rows rg and rg+8) =====
    {
        int l0 = wi * 16 + rg;
        const float* mr0 = maskp + ((size_t)(bb * S_ + e * SEG_ + l0)) * S_
                                 + (size_t)e * SEG_;
        const float* mr1 = mr0 + (size_t)8 * S_;
        #pragma unroll
        for (int j = 0; j < 16; j++) {
            float2 m0 = *(const float2*)(mr0 + 8 * j + tg * 2);
            float2 m1 = *(const float2*)(mr1 + 8 * j + tg * 2);
            if (fixe && l0 == 0) { m0.x = 0.0f; m0.y = 0.0f; }
            accB[j][0] += m0.x; accB[j][1] += m0.y;
            accB[j][2] += m1.x; accB[j][3] += m1.y;
        }
        float mx0 = -3.4e38f, mx1 = -3.4e38f;
        #pragma unroll
        for (int j = 0; j < 16; j++) {
            mx0 = fmaxf(mx0, fmaxf(accB[j][0], accB[j][1]));
            mx1 = fmaxf(mx1, fmaxf(accB[j][2], accB[j][3]));
        }
        mx0 = fmaxf(mx0, __shfl_xor_sync(0xffffffffu, mx0, 1));
        mx0 = fmaxf(mx0, __shfl_xor_sync(0xffffffffu, mx0, 2));
        mx1 = fmaxf(mx1, __shfl_xor_sync(0xffffffffu, mx1, 1));
        mx1 = fmaxf(mx1, __shfl_xor_sync(0xffffffffu, mx1, 2));
        float s0 = 0.0f, s1 = 0.0f;
        #pragma unroll
        for (int j = 0; j < 16; j++) {
            accB[j][0] = expf(accB[j][0] - mx0);
            accB[j][1] = expf(accB[j][1] - mx0);
            accB[j][2] = expf(accB[j][2] - mx1);
            accB[j][3] = expf(accB[j][3] - mx1);
            s0 += accB[j][0] + accB[j][1];
            s1 += accB[j][2] + accB[j][3];
        }
        s0 += __shfl_xor_sync(0xffffffffu, s0, 1);
        s0 += __shfl_xor_sync(0xffffffffu, s0, 2);
        s1 += __shfl_xor_sync(0xffffffffu, s1, 1);
        s1 += __shfl_xor_sync(0xffffffffu, s1, 2);
        float i0 = 1.0f / s0, i1 = 1.0f / s1;
        #pragma unroll
        for (int j = 0; j < 16; j++) {
            accB[j][0] *= i0; accB[j][1] *= i0;
            accB[j][2] *= i1; accB[j][3] *= i1;
        }
    }

    // pack attn to phase-C A-frags (pAh/pAl dead now)
    unsigned aCh[32], aCl[32];
    #pragma unroll
    for (int j = 0; j < 16; j++) {
        int base = (j >> 1) * 4 + (j & 1) * 2;
        aCh[base]     = packhi(accB[j][0], accB[j][1]);
        aCl[base]     = packlo(accB[j][0], accB[j][1], aCh[base]);
        aCh[base + 1] = packhi(accB[j][2], accB[j][3]);
        aCl[base + 1] = packlo(accB[j][2], accB[j][3], aCh[base + 1]);
    }

    // =========== Phase C: ctx(16 rows x 256 d) = attn @ seq, pooled =======
    #pragma unroll
    for (int half = 0; half < 2; half++) {
        float accC[16][4];
        #pragma unroll
        for (int j = 0; j < 16; j++)
            #pragma unroll
            for (int q = 0; q < 4; q++) accC[j][q] = 0.0f;

        #pragma unroll
        for (int kc = 0; kc < 8; kc++) {
            #pragma unroll
            for (int p = 0; p < 8; p++) {
                unsigned bh0, bh1, bh2, bh3, bl0, bl1, bl2, bl3;
                ldsm4t(adrBt(OFF_SEQ_H, SEQ_ST, kc * 16, half * 128 + p * 16),
                       bh0, bh1, bh2, bh3);
                ldsm4t(adrBt(OFF_SEQ_L, SEQ_ST, kc * 16, half * 128 + p * 16),
                       bl0, bl1, bl2, bl3);
                mma16816(accC[2*p],   aCh[kc*4], aCh[kc*4+1], aCh[kc*4+2], aCh[kc*4+3], bh0, bh1);
                mma16816(accC[2*p],   aCh[kc*4], aCh[kc*4+1], aCh[kc*4+2], aCh[kc*4+3], bl0, bl1);
                mma16816(accC[2*p],   aCl[kc*4], aCl[kc*4+1], aCl[kc*4+2], aCl[kc*4+3], bh0, bh1);
                mma16816(accC[2*p+1], aCh[kc*4], aCh[kc*4+1], aCh[kc*4+2], aCh[kc*4+3], bh2, bh3);
                mma16816(accC[2*p+1], aCh[kc*4], aCh[kc*4+1], aCh[kc*4+2], aCh[kc*4+3], bl2, bl3);
                mma16816(accC[2*p+1], aCl[kc*4], aCl[kc*4+1], aCl[kc*4+2], aCl[kc*4+3], bh2, bh3);
            }
        }
        #pragma unroll
        for (int j = 0; j < 16; j++) {
            float m0 = fmaxf(accC[j][0], accC[j][2]);
            float m1 = fmaxf(accC[j][1], accC[j][3]);
            m0 = fmaxf(m0, __shfl_xor_sync(0xffffffffu, m0, 4));
            m0 = fmaxf(m0, __shfl_xor_sync(0xffffffffu, m0, 8));
            m0 = fmaxf(m0, __shfl_xor_sync(0xffffffffu, m0, 16));
            m1 = fmaxf(m1, __shfl_xor_sync(0xffffffffu, m1, 4));
            m1 = fmaxf(m1, __shfl_xor_sync(0xffffffffu, m1, 8));
            m1 = fmaxf(m1, __shfl_xor_sync(0xffffffffu, m1, 16));
            if (rg == 0) {
                int d = half * 128 + 8 * j + tg * 2;
                pool[wi * 256 + d]     = m0;
                pool[wi * 256 + d + 1] = m1;
            }
        }
    }
    __syncthreads();

    // ---- final pool reduce over 8 warps ----
    {
        float mx = -3.4e38f;
        #pragma unroll
        for (int w = 0; w < 8; w++) mx = fmaxf(mx, pool[w * 256 + t]);
        out[((size_t)bb * E_ + e) * D_ + t] = mx;
    }

    // new_mask[b][e][s] = (s/128 == e)
    float* nm = out + (size_t)B_ * E_ * D_ + ((size_t)bb * E_ + e) * S_;
    for (int s = t; s < S_; s += 256)
        nm[s] = ((s >> 7) == e) ? 1.0f : 0.0f;
}

// ---------------------------------------------------------------------------
extern "C" void kernel_launch(void* const* d_in, const int* in_sizes, int n_in,
                              void* d_out, int out_size) {
    const float* hidden = (const float*)d_in[0];
    const float* mask   = (const float*)d_in[1];
    const float* w      = (const float*)d_in[2];
    const float* bvec   = (const float*)d_in[3];
    float* out = (float*)d_out;
    (void)in_sizes; (void)n_in; (void)out_size;

    prep_fix_kernel<<<E_, 256>>>(w, mask);

    cudaFuncSetAttribute(main_kernel,
                         cudaFuncAttributeMaxDynamicSharedMemorySize, SMEM_TOT);
    main_kernel<<<dim3(E_, B_), 256, SMEM_TOT>>>(hidden, mask, bvec, out);
}

// round 12
// speedup vs baseline: 1.4819x; 1.0178x over previous
#include <cuda_runtime.h>
#include <cuda_bf16.h>
#include <math.h>
#include <stdint.h>

#define B_   8
#define S_   4096
#define D_   256
#define SEG_ 128
#define E_   32
#define MASKVAL (-3.402823466e38f)

#define SEQ_ST 264   // halves
#define WB_ST  72    // halves (144B row stride: conflict-free ldsm)

// smem byte offsets
#define OFF_SEQ_H 0          // 128*264*2 = 67584
#define OFF_SEQ_L 67584      // ends 135168
#define OFF_WBUF  135168     // 2 bufs x 36864 = 73728, ends 208896
#define OFF_BIAS  208896     // 1024
#define OFF_POOL  209920     // 8*256*4 = 8192
#define SMEM_TOT  218112

// w packed per chunk j = h*4 + c (h = m-half, c = 64-wide k chunk):
// [j]{ hi: m 0..127 x 72 halves | lo: same } = 18432 halves (36864 B) per chunk
__device__ __nv_bfloat16 g_w[8 * 18432];
__device__ int g_fix[E_];

// ---------------------------------------------------------------------------
__global__ void prep_fix_kernel(const float* __restrict__ w,
                                const float* __restrict__ mask) {
    int e = blockIdx.x, t = threadIdx.x;
    #pragma unroll
    for (int i = 0; i < 8; i++) {
        int idx = (e * 256 + t) + i * 8192;       // 65536 total
        int m = idx >> 8, d = idx & 255;
        float v = w[idx];
        __nv_bfloat16 h = __float2bfloat16(v);
        __nv_bfloat16 l = __float2bfloat16(v - __bfloat162float(h));
        int hh = m >> 7, mloc = m & 127, c = d >> 6, kk = d & 63;
        int j = hh * 4 + c;
        int off = j * 18432 + mloc * 72 + kk;
        g_w[off] = h;
        g_w[off + 9216] = l;
    }
    if (t == 0) g_fix[e] = 0;
    __syncthreads();

    int warp = t >> 5, lane = t & 31;
    int found = 0;
    for (int r = warp; r < B_ * SEG_; r += 8) {
        int b = r >> 7, l = r & 127;
        const float* row = mask + ((size_t)b * S_ + (size_t)e * SEG_ + l) * S_
                                + (size_t)e * SEG_;
        int allm = 1;
        #pragma unroll
        for (int k = 0; k < 4; k++)
            if (row[lane + 32 * k] != MASKVAL) allm = 0;
        if (__all_sync(0xffffffffu, allm)) { found = 1; break; }
    }
    if (found && lane == 0) atomicOr(&g_fix[e], 1);
}

// ---------------------------------------------------------------------------
__device__ __forceinline__ void ldsm4(unsigned a, unsigned& r0, unsigned& r1,
                                      unsigned& r2, unsigned& r3) {
    asm volatile("ldmatrix.sync.aligned.m8n8.x4.shared.b16 {%0,%1,%2,%3},[%4];"
                 : "=r"(r0), "=r"(r1), "=r"(r2), "=r"(r3) : "r"(a));
}
__device__ __forceinline__ void ldsm4t(unsigned a, unsigned& r0, unsigned& r1,
                                       unsigned& r2, unsigned& r3) {
    asm volatile("ldmatrix.sync.aligned.m8n8.x4.trans.shared.b16 {%0,%1,%2,%3},[%4];"
                 : "=r"(r0), "=r"(r1), "=r"(r2), "=r"(r3) : "r"(a));
}
__device__ __forceinline__ void mma16816(float* c, unsigned a0, unsigned a1,
                                         unsigned a2, unsigned a3,
                                         unsigned b0, unsigned b1) {
    asm volatile(
        "mma.sync.aligned.m16n8k16.row.col.f32.bf16.bf16.f32 "
        "{%0,%1,%2,%3},{%4,%5,%6,%7},{%8,%9},{%0,%1,%2,%3};"
        : "+f"(c[0]), "+f"(c[1]), "+f"(c[2]), "+f"(c[3])
        : "r"(a0), "r"(a1), "r"(a2), "r"(a3), "r"(b0), "r"(b1));
}
__device__ __forceinline__ unsigned packhi(float a, float b) {
    __nv_bfloat162 p;
    p.x = __float2bfloat16(a); p.y = __float2bfloat16(b);
    return *(unsigned*)&p;
}
__device__ __forceinline__ unsigned packlo(float a, float b, unsigned hi) {
    __nv_bfloat162 h = *(__nv_bfloat162*)&hi;
    __nv_bfloat162 p;
    p.x = __float2bfloat16(a - __bfloat162float(h.x));
    p.y = __float2bfloat16(b - __bfloat162float(h.y));
    return *(unsigned*)&p;
}
__device__ __forceinline__ void cpasync16(unsigned dst, const void* src) {
    asm volatile("cp.async.cg.shared.global [%0],[%1],16;"
                 :: "r"(dst), "l"(src));
}
#define CP_COMMIT() asm volatile("cp.async.commit_group;" ::: "memory")
#define CP_WAIT0()  asm volatile("cp.async.wait_group 0;" ::: "memory")

// ---------------------------------------------------------------------------
__global__ void __launch_bounds__(256, 1)
main_kernel(const float* __restrict__ hidden,
            const float* __restrict__ maskp,
            const float* __restrict__ bvec,
            float* __restrict__ out)
{
    extern __shared__ char smc[];
    const unsigned sb = (unsigned)__cvta_generic_to_shared(smc);

    float* bias = (float*)(smc + OFF_BIAS);
    float* pool = (float*)(smc + OFF_POOL);

    const int t = threadIdx.x;
    const int lane = t & 31, wi = t >> 5;
    const int rg = lane >> 2, tg = lane & 3;
    const int e = blockIdx.x, bb = blockIdx.y;

    // ---- kick off w chunk 0 (cp.async, overlaps seq load) ----
    auto load_chunk = [&](int j, int bufi) {
        unsigned dst = sb + OFF_WBUF + (unsigned)bufi * 36864 + (unsigned)t * 16;
        const char* src = (const char*)g_w + (size_t)j * 36864 + (size_t)t * 16;
        #pragma unroll
        for (int i = 0; i < 9; i++)
            cpasync16(dst + i * 4096, src + i * 4096);
        CP_COMMIT();
    };
    load_chunk(0, 0);

    // ---- load seq tile, split bf16 hi/lo ----
    const float* seq_g = hidden + ((size_t)bb * S_ + (size_t)e * SEG_) * D_;
    for (int i = t; i < SEG_ * D_ / 4; i += 256) {
        int l = i >> 6, d = (i & 63) << 2;
        float4 v = *(const float4*)(seq_g + l * D_ + d);
        __nv_bfloat162 h0, h1, l0, l1;
        h0.x = __float2bfloat16(v.x); h0.y = __float2bfloat16(v.y);
        h1.x = __float2bfloat16(v.z); h1.y = __float2bfloat16(v.w);
        l0.x = __float2bfloat16(v.x - __bfloat162float(h0.x));
        l0.y = __float2bfloat16(v.y - __bfloat162float(h0.y));
        l1.x = __float2bfloat16(v.z - __bfloat162float(h1.x));
        l1.y = __float2bfloat16(v.w - __bfloat162float(h1.y));
        __nv_bfloat16* sh = (__nv_bfloat16*)(smc + OFF_SEQ_H) + l * SEQ_ST + d;
        __nv_bfloat16* sl = (__nv_bfloat16*)(smc + OFF_SEQ_L) + l * SEQ_ST + d;
        *(__nv_bfloat162*)sh = h0; *(__nv_bfloat162*)(sh + 2) = h1;
        *(__nv_bfloat162*)sl = l0; *(__nv_bfloat162*)(sl + 2) = l1;
    }
    bias[t] = bvec[t];
    const int fixe = g_fix[e];

    auto adrA = [&](unsigned off, int st, int r0, int k0) -> unsigned {
        int r = r0 + (lane & 7) + ((lane >> 3) & 1) * 8;
        int c = k0 + ((lane >> 4) & 1) * 8;
        return sb + off + (unsigned)((r * st + c) * 2);
    };
    auto adrB = [&](unsigned off, int st, int n0, int k0) -> unsigned {
        int r = n0 + (lane & 7) + ((lane >> 4) & 1) * 8;
        int c = k0 + ((lane >> 3) & 1) * 8;
        return sb + off + (unsigned)((r * st + c) * 2);
    };
    auto adrBt = [&](unsigned off, int st, int k0, int d0) -> unsigned {
        int r = k0 + (lane & 7) + ((lane >> 3) & 1) * 8;
        int c = d0 + ((lane >> 4) & 1) * 8;
        return sb + off + (unsigned)((r * st + c) * 2);
    };

    // =========== Phase A: trsf = tanh(seq @ w^T + b), streamed ============
    unsigned pAh[64], pAl[64];              // trsf A-frags, full 256 m
    float accA[16][4];

    // init accA[jj] = bias (half 0) after first barrier; done inside loop j==0
    for (int j = 0; j < 8; j++) {           // chunk: h = j>>2, k64 = j&3
        CP_WAIT0();
        __syncthreads();
        if (j < 7) load_chunk(j + 1, (j + 1) & 1);

        if ((j & 3) == 0) {
            // start of m-half: init acc with bias
            int h = j >> 2;
            #pragma unroll
            for (int jj = 0; jj < 16; jj++) {
                int m0 = h * 128 + jj * 8 + tg * 2;
                float b0 = bias[m0], b1 = bias[m0 + 1];
                accA[jj][0] = b0; accA[jj][1] = b1;
                accA[jj][2] = b0; accA[jj][3] = b1;
            }
        }

        unsigned bufB = OFF_WBUF + (unsigned)(j & 1) * 36864;
        #pragma unroll
        for (int kl = 0; kl < 4; kl++) {
            int kq = (j & 3) * 4 + kl;      // seq k-step 0..15
            unsigned ah0, ah1, ah2, ah3, am0, am1, am2, am3;
            ldsm4(adrA(OFF_SEQ_H, SEQ_ST, wi * 16, kq * 16), ah0, ah1, ah2, ah3);
            ldsm4(adrA(OFF_SEQ_L, SEQ_ST, wi * 16, kq * 16), am0, am1, am2, am3);
            #pragma unroll
            for (int p = 0; p < 8; p++) {
                unsigned bh0, bh1, bh2, bh3, bl0, bl1, bl2, bl3;
                ldsm4(adrB(bufB, WB_ST, p * 16, kl * 16), bh0, bh1, bh2, bh3);
                ldsm4(adrB(bufB + 18432, WB_ST, p * 16, kl * 16), bl0, bl1, bl2, bl3);
                mma16816(accA[2*p],   ah0, ah1, ah2, ah3, bh0, bh1);
                mma16816(accA[2*p],   ah0, ah1, ah2, ah3, bl0, bl1);
                mma16816(accA[2*p],   am0, am1, am2, am3, bh0, bh1);
                mma16816(accA[2*p+1], ah0, ah1, ah2, ah3, bh2, bh3);
                mma16816(accA[2*p+1], ah0, ah1, ah2, ah3, bl2, bl3);
                mma16816(accA[2*p+1], am0, am1, am2, am3, bh2, bh3);
            }
        }

        if ((j & 3) == 3) {
            // epilogue for m-half h: tanh, pack hi/lo frags to regs
            int h = j >> 2;
            #pragma unroll
            for (int jj = 0; jj < 16; jj++) {
                float v0 = tanhf(accA[jj][0]), v1 = tanhf(accA[jj][1]);
                float v2 = tanhf(accA[jj][2]), v3 = tanhf(accA[jj][3]);
                int base = h * 32 + (jj >> 1) * 4 + (jj & 1) * 2;
                pAh[base]     = packhi(v0, v1);
                pAl[base]     = packlo(v0, v1, pAh[base]);
                pAh[base + 1] = packhi(v2, v3);
                pAl[base + 1] = packlo(v2, v3, pAh[base + 1]);
            }
        }
    }

    // =========== Phase B: scores(16 rows x 128 k) = trsf @ seq^T ==========
    // accB initialized from mask (+fix) so the global loads hide under MMAs.
    float accB[16][4];
    {
        int l0 = wi * 16 + rg;
        const float* mr0 = maskp + ((size_t)(bb * S_ + e * SEG_ + l0)) * S_
                                 + (size_t)e * SEG_;
        const float* mr1 = mr0 + (size_t)8 * S_;
        #pragma unroll
        for (int j = 0; j < 16; j++) {
            float2 m0 = *(const float2*)(mr0 + 8 * j + tg * 2);
            float2 m1 = *(const float2*)(mr1 + 8 * j + tg * 2);
            if (fixe && l0 == 0) { m0.x = 0.0f; m0.y = 0.0f; }
            accB[j][0] = m0.x; accB[j][1] = m0.y;
            accB[j][2] = m1.x; accB[j][3] = m1.y;
        }
    }

    #pragma unroll
    for (int kc = 0; kc < 16; kc++) {
        #pragma unroll
        for (int p = 0; p < 8; p++) {
            unsigned bh0, bh1, bh2, bh3, bl0, bl1, bl2, bl3;
            ldsm4(adrB(OFF_SEQ_H, SEQ_ST, p * 16, kc * 16), bh0, bh1, bh2, bh3);
            ldsm4(adrB(OFF_SEQ_L, SEQ_ST, p * 16, kc * 16), bl0, bl1, bl2, bl3);
            mma16816(accB[2*p],   pAh[kc*4], pAh[kc*4+1], pAh[kc*4+2], pAh[kc*4+3], bh0, bh1);
            mma16816(accB[2*p],   pAh[kc*4], pAh[kc*4+1], pAh[kc*4+2], pAh[kc*4+3], bl0, bl1);
            mma16816(accB[2*p],   pAl[kc*4], pAl[kc*4+1], pAl[kc*4+2], pAl[kc*4+3], bh0, bh1);
            mma16816(accB[2*p+1], pAh[kc*4], pAh[kc*4+1], pAh[kc*4+2], pAh[kc*4+3], bh2, bh3);
            mma16816(accB[2*p+1], pAh[kc*4], pAh[kc*4+1], pAh[kc*4+2], pAh[kc*4+3], bl2, bl3);
            mma16816(accB[2*p+1], pAl[kc*4], pAl[kc*4+1], pAl[kc*4+2], pAl[kc*4+3], bh2, bh3);
        }
    }

    // ===== in-register softmax (rows rg and rg+8) =====
    {
        float mx0 = -3.4e38f, mx1 = -3.4e38f;
        #pragma unroll
        for (int j = 0; j < 16; j++) {
            mx0 = fmaxf(mx0, fmaxf(accB[j][0], accB[j][1]));
            mx1 = fmaxf(mx1, fmaxf(accB[j][2], accB[j][3]));
        }
        mx0 = fmaxf(mx0, __shfl_xor_sync(0xffffffffu, mx0, 1));
        mx0 = fmaxf(mx0, __shfl_xor_sync(0xffffffffu, mx0, 2));
        mx1 = fmaxf(mx1, __shfl_xor_sync(0xffffffffu, mx1, 1));
        mx1 = fmaxf(mx1, __shfl_xor_sync(0xffffffffu, mx1, 2));
        float s0 = 0.0f, s1 = 0.0f;
        #pragma unroll
        for (int j = 0; j < 16; j++) {
            accB[j][0] = __expf(accB[j][0] - mx0);
            accB[j][1] = __expf(accB[j][1] - mx0);
            accB[j][2] = __expf(accB[j][2] - mx1);
            accB[j][3] = __expf(accB[j][3] - mx1);
            s0 += accB[j][0] + accB[j][1];
            s1 += accB[j][2] + accB[j][3];
        }
        s0 += __shfl_xor_sync(0xffffffffu, s0, 1);
        s0 += __shfl_xor_sync(0xffffffffu, s0, 2);
        s1 += __shfl_xor_sync(0xffffffffu, s1, 1);
        s1 += __shfl_xor_sync(0xffffffffu, s1, 2);
        float i0 = 1.0f / s0, i1 = 1.0f / s1;
        #pragma unroll
        for (int j = 0; j < 16; j++) {
            accB[j][0] *= i0; accB[j][1] *= i0;
            accB[j][2] *= i1; accB[j][3] *= i1;
        }
    }

    // pack attn to phase-C A-frags (pAh/pAl dead now)
    unsigned aCh[32], aCl[32];
    #pragma unroll
    for (int j = 0; j < 16; j++) {
        int base = (j >> 1) * 4 + (j & 1) * 2;
        aCh[base]     = packhi(accB[j][0], accB[j][1]);
        aCl[base]     = packlo(accB[j][0], accB[j][1], aCh[base]);
        aCh[base + 1] = packhi(accB[j][2], accB[j][3]);
        aCl[base + 1] = packlo(accB[j][2], accB[j][3], aCh[base + 1]);
    }

    // =========== Phase C: ctx(16 rows x 256 d) = attn @ seq, pooled =======
    #pragma unroll
    for (int half = 0; half < 2; half++) {
        float accC[16][4];
        #pragma unroll
        for (int j = 0; j < 16; j++)
            #pragma unroll
            for (int q = 0; q < 4; q++) accC[j][q] = 0.0f;

        #pragma unroll
        for (int kc = 0; kc < 8; kc++) {
            #pragma unroll
            for (int p = 0; p < 8; p++) {
                unsigned bh0, bh1, bh2, bh3, bl0, bl1, bl2, bl3;
                ldsm4t(adrBt(OFF_SEQ_H, SEQ_ST, kc * 16, half * 128 + p * 16),
                       bh0, bh1, bh2, bh3);
                ldsm4t(adrBt(OFF_SEQ_L, SEQ_ST, kc * 16, half * 128 + p * 16),
                       bl0, bl1, bl2, bl3);
                mma16816(accC[2*p],   aCh[kc*4], aCh[kc*4+1], aCh[kc*4+2], aCh[kc*4+3], bh0, bh1);
                mma16816(accC[2*p],   aCh[kc*4], aCh[kc*4+1], aCh[kc*4+2], aCh[kc*4+3], bl0, bl1);
                mma16816(accC[2*p],   aCl[kc*4], aCl[kc*4+1], aCl[kc*4+2], aCl[kc*4+3], bh0, bh1);
                mma16816(accC[2*p+1], aCh[kc*4], aCh[kc*4+1], aCh[kc*4+2], aCh[kc*4+3], bh2, bh3);
                mma16816(accC[2*p+1], aCh[kc*4], aCh[kc*4+1], aCh[kc*4+2], aCh[kc*4+3], bl2, bl3);
                mma16816(accC[2*p+1], aCl[kc*4], aCl[kc*4+1], aCl[kc*4+2], aCl[kc*4+3], bh2, bh3);
            }
        }
        #pragma unroll
        for (int j = 0; j < 16; j++) {
            float m0 = fmaxf(accC[j][0], accC[j][2]);
            float m1 = fmaxf(accC[j][1], accC[j][3]);
            m0 = fmaxf(m0, __shfl_xor_sync(0xffffffffu, m0, 4));
            m0 = fmaxf(m0, __shfl_xor_sync(0xffffffffu, m0, 8));
            m0 = fmaxf(m0, __shfl_xor_sync(0xffffffffu, m0, 16));
            m1 = fmaxf(m1, __shfl_xor_sync(0xffffffffu, m1, 4));
            m1 = fmaxf(m1, __shfl_xor_sync(0xffffffffu, m1, 8));
            m1 = fmaxf(m1, __shfl_xor_sync(0xffffffffu, m1, 16));
            if (rg == 0) {
                int d = half * 128 + 8 * j + tg * 2;
                pool[wi * 256 + d]     = m0;
                pool[wi * 256 + d + 1] = m1;
            }
        }
    }
    __syncthreads();

    // ---- final pool reduce over 8 warps ----
    {
        float mx = -3.4e38f;
        #pragma unroll
        for (int w = 0; w < 8; w++) mx = fmaxf(mx, pool[w * 256 + t]);
        out[((size_t)bb * E_ + e) * D_ + t] = mx;
    }

    // new_mask[b][e][s] = (s/128 == e)
    float* nm = out + (size_t)B_ * E_ * D_ + ((size_t)bb * E_ + e) * S_;
    for (int s = t; s < S_; s += 256)
        nm[s] = ((s >> 7) == e) ? 1.0f : 0.0f;
}

// ---------------------------------------------------------------------------
extern "C" void kernel_launch(void* const* d_in, const int* in_sizes, int n_in,
                              void* d_out, int out_size) {
    const float* hidden = (const float*)d_in[0];
    const float* mask   = (const float*)d_in[1];
    const float* w      = (const float*)d_in[2];
    const float* bvec   = (const float*)d_in[3];
    float* out = (float*)d_out;
    (void)in_sizes; (void)n_in; (void)out_size;

    prep_fix_kernel<<<E_, 256>>>(w, mask);

    cudaFuncSetAttribute(main_kernel,
                         cudaFuncAttributeMaxDynamicSharedMemorySize, SMEM_TOT);
    main_kernel<<<dim3(E_, B_), 256, SMEM_TOT>>>(hidden, mask, bvec, out);
}